// round 10
// baseline (speedup 1.0000x reference)
#include <cuda_runtime.h>
#include <cuda_fp16.h>
#include <cstdint>

// D[b,o] = sum_ck A[b,ck] * W[o,ck] — GEMM M=256, N=1024, K=16384, fp32 I/O.
// fp16 operands (converted at STS), fp32 accumulate, mma.sync m16n8k16.
// R4 base (measured best GEMM 47.6us): 512 threads / 16 warps, 128x128 CTA
// tile, 32x32 warp tiles, TILE_K=32, double-buffered smem, 2-deep fp32
// register staging, separate reduce kernel.
// R10 change: iteration reordered LDSM-all -> STS -> LDG -> MMA -> BAR so the
// MMA block covers the STS drain and LDG issue (removes ~160cyc exposed STS).
#define B_DIM   256
#define N_DIM   1024
#define K_DIM   16384
#define TILE_M  128
#define TILE_N  128
#define TILE_K  32
#define SPLITK  8
#define K_PER_CTA (K_DIM / SPLITK)       // 2048
#define NITER   (K_PER_CTA / TILE_K)     // 64
#define NTHREADS 512

// Smem tile: 128 rows x 32 halfs (64 B), padded stride 80 B (16-aligned;
// 80*r mod 128 covers 8 distinct 16B banks -> conflict-free ldmatrix).
#define ROW_HB   80
#define TILE_HB  (128 * ROW_HB)           // 10240 B
#define STAGE_HB (2 * TILE_HB)            // A + B per stage
#define SMEM_BYTES (2 * STAGE_HB)         // double buffer = 40960 B

__device__ float g_part[SPLITK * B_DIM * N_DIM];

__device__ __forceinline__ uint32_t smem_u32(const void* p) {
    uint32_t a;
    asm("{ .reg .u64 t; cvta.to.shared.u64 t, %1; cvt.u32.u64 %0, t; }" : "=r"(a) : "l"(p));
    return a;
}

__device__ __forceinline__ void ldmx4(uint32_t* r, uint32_t addr) {
    asm volatile("ldmatrix.sync.aligned.m8n8.x4.shared.b16 {%0,%1,%2,%3}, [%4];"
                 : "=r"(r[0]), "=r"(r[1]), "=r"(r[2]), "=r"(r[3]) : "r"(addr));
}

__device__ __forceinline__ void mma16816(float* d, const uint32_t* a, const uint32_t* b) {
    asm volatile(
        "mma.sync.aligned.m16n8k16.row.col.f32.f16.f16.f32 "
        "{%0,%1,%2,%3}, {%4,%5,%6,%7}, {%8,%9}, {%0,%1,%2,%3};"
        : "+f"(d[0]), "+f"(d[1]), "+f"(d[2]), "+f"(d[3])
        : "r"(a[0]), "r"(a[1]), "r"(a[2]), "r"(a[3]), "r"(b[0]), "r"(b[1]));
}

__device__ __forceinline__ uint2 pack4h(float4 v) {
    __half2 lo = __floats2half2_rn(v.x, v.y);
    __half2 hi = __floats2half2_rn(v.z, v.w);
    uint2 r;
    r.x = *(uint32_t*)&lo;
    r.y = *(uint32_t*)&hi;
    return r;
}

__global__ void __launch_bounds__(NTHREADS, 1)
StreamingConv_gemm_kernel(const float* __restrict__ A, const float* __restrict__ W)
{
    __shared__ __align__(16) char smem[SMEM_BYTES];
    const uint32_t sb = smem_u32(smem);

    const int tid = threadIdx.x;
    const int lane = tid & 31;
    const int wid = tid >> 5;
    const int wm = wid >> 2;          // 0..3 -> 32-row band of M
    const int wn = wid & 3;           // 0..3 -> 32-col band of N

    const int m0 = blockIdx.y * TILE_M;
    const int n0 = blockIdx.x * TILE_N;
    const int sk = blockIdx.z;
    const size_t kbase = (size_t)sk * K_PER_CTA;

    // ---- gmem load mapping: 2 float4 for A + 2 for W per thread per iter ----
    const float* pa[2];
    const float* pb[2];
    uint32_t sts_off[2];
    #pragma unroll
    for (int i = 0; i < 2; i++) {
        const int idx = tid + NTHREADS * i;
        const int row = idx >> 3;     // 0..127
        const int c4  = idx & 7;      // float4 within 32-float row
        pa[i] = A + (size_t)(m0 + row) * K_DIM + kbase + c4 * 4;
        pb[i] = W + (size_t)(n0 + row) * K_DIM + kbase + c4 * 4;
        sts_off[i] = (uint32_t)(row * ROW_HB + c4 * 8);   // 4 halfs = 8 B
    }

    // ---- ldmatrix per-lane tile offsets (add ks*32 at use) ----
    uint32_t a_off[2];
    #pragma unroll
    for (int mt = 0; mt < 2; mt++)
        a_off[mt] = (uint32_t)((wm * 32 + mt * 16 + (lane & 15)) * ROW_HB + (lane >> 4) * 16);
    uint32_t b_off[2];
    #pragma unroll
    for (int p = 0; p < 2; p++)
        b_off[p] = (uint32_t)((wn * 32 + (2 * p + (lane >> 4)) * 8 + (lane & 7)) * ROW_HB
                              + ((lane >> 3) & 1) * 16);

    float acc[2][4][4];
    #pragma unroll
    for (int mt = 0; mt < 2; mt++)
        #pragma unroll
        for (int nt = 0; nt < 4; nt++)
            #pragma unroll
            for (int j = 0; j < 4; j++) acc[mt][nt][j] = 0.f;

    // ---- 2-deep register staging queue (raw fp32; cvt at STS) ----
    float4 qa[2][2], qb[2][2];
    #pragma unroll
    for (int d = 0; d < 2; d++) {
        const size_t ko = (size_t)d * TILE_K;
        #pragma unroll
        for (int i = 0; i < 2; i++) {
            qa[d][i] = *(const float4*)(pa[i] + ko);
            qb[d][i] = *(const float4*)(pb[i] + ko);
        }
    }
    #pragma unroll
    for (int i = 0; i < 2; i++) {
        *(uint2*)(smem + sts_off[i])           = pack4h(qa[0][i]);
        *(uint2*)(smem + TILE_HB + sts_off[i]) = pack4h(qb[0][i]);
    }
    __syncthreads();

    #pragma unroll 2
    for (int it = 0; it < NITER; ++it) {
        const uint32_t baseA = sb + (uint32_t)(it & 1) * STAGE_HB;
        const uint32_t baseB = baseA + TILE_HB;

        // 1) load ALL fragments for both k16 steps (LDSM latency overlapped below)
        uint32_t afr[2][2][4], bfr[2][2][4];    // [ks][mt/p][4]
        #pragma unroll
        for (int ks = 0; ks < 2; ks++) {
            #pragma unroll
            for (int mt = 0; mt < 2; mt++) ldmx4(afr[ks][mt], baseA + a_off[mt] + ks * 32);
            #pragma unroll
            for (int p = 0; p < 2; p++)  ldmx4(bfr[ks][p], baseB + b_off[p] + ks * 32);
        }

        // 2) convert + store chunk it+1 into the other stage (drains during MMA)
        if (it + 1 < NITER) {
            const uint32_t nxt = (uint32_t)((it + 1) & 1) * STAGE_HB;
            const int d = (it + 1) & 1;
            #pragma unroll
            for (int i = 0; i < 2; i++) {
                *(uint2*)(smem + nxt + sts_off[i])           = pack4h(qa[d][i]);
                *(uint2*)(smem + nxt + TILE_HB + sts_off[i]) = pack4h(qb[d][i]);
            }
        }

        // 3) LDG chunk it+2 into the queue slot just freed
        if (it + 2 < NITER) {
            const size_t ko = (size_t)(it + 2) * TILE_K;
            const int d = it & 1;
            #pragma unroll
            for (int i = 0; i < 2; i++) {
                qa[d][i] = *(const float4*)(pa[i] + ko);
                qb[d][i] = *(const float4*)(pb[i] + ko);
            }
        }

        // 4) MMAs (cover STS drain + LDG issue)
        #pragma unroll
        for (int ks = 0; ks < 2; ks++)
            #pragma unroll
            for (int mt = 0; mt < 2; mt++)
                #pragma unroll
                for (int nt = 0; nt < 4; nt++) {
                    uint32_t bb[2] = { bfr[ks][nt >> 1][(nt & 1) * 2],
                                       bfr[ks][nt >> 1][(nt & 1) * 2 + 1] };
                    mma16816(acc[mt][nt], afr[ks][mt], bb);
                }

        __syncthreads();
    }

    // ---- write split-K partials ----
    float* pbase = &g_part[(size_t)sk * (B_DIM * N_DIM)];
    #pragma unroll
    for (int mt = 0; mt < 2; mt++) {
        const int row0 = m0 + wm * 32 + mt * 16 + (lane >> 2);
        #pragma unroll
        for (int nt = 0; nt < 4; nt++) {
            const int col = n0 + wn * 32 + nt * 8 + 2 * (lane & 3);
            *(float2*)&pbase[(size_t)row0 * N_DIM + col]       = make_float2(acc[mt][nt][0], acc[mt][nt][1]);
            *(float2*)&pbase[(size_t)(row0 + 8) * N_DIM + col] = make_float2(acc[mt][nt][2], acc[mt][nt][3]);
        }
    }
}

__global__ void StreamingConv_reduce_kernel(float* __restrict__ out)
{
    const int idx = blockIdx.x * blockDim.x + threadIdx.x;   // float4 index
    const float4* p = (const float4*)g_part;
    float4 acc = p[idx];
    #pragma unroll
    for (int i = 1; i < SPLITK; i++) {
        const float4 v = p[(size_t)i * (B_DIM * N_DIM / 4) + idx];
        acc.x += v.x; acc.y += v.y; acc.z += v.z; acc.w += v.w;
    }
    ((float4*)out)[idx] = acc;
}

extern "C" void kernel_launch(void* const* d_in, const int* in_sizes, int n_in,
                              void* d_out, int out_size)
{
    const float* A = (const float*)d_in[0];   // curr_input [256, 1024, 16]
    const float* W = (const float*)d_in[1];   // weight     [1024, 1024, 16]

    dim3 grid(N_DIM / TILE_N, B_DIM / TILE_M, SPLITK);   // (8, 2, 8) = 128 CTAs
    StreamingConv_gemm_kernel<<<grid, NTHREADS>>>(A, W);
    StreamingConv_reduce_kernel<<<(B_DIM * N_DIM / 4) / 256, 256>>>((float*)d_out);
}

// round 11
// speedup vs baseline: 1.0323x; 1.0323x over previous
#include <cuda_runtime.h>
#include <cuda_fp16.h>
#include <cstdint>

// D[b,o] = sum_ck A[b,ck] * W[o,ck] — GEMM M=256, N=1024, K=16384, fp32 I/O.
// fp16 operands (converted at STS), fp32 accumulate, mma.sync m16n8k16.
// R4 base (measured best GEMM 47.6us): 512 threads / 16 warps, 128x128 CTA
// tile, 32x32 warp tiles, TILE_K=32, double-buffered smem, 2-deep fp32
// register staging. regs sit exactly at the 128/thread RF wall — all changes
// must keep peak live registers <= R4's.
// R11 changes: (1) STS of chunk it+1 moved BETWEEN the two k16 MMA halves so
// the ks1 MMA block covers the STS drain (R4 exposed it before the barrier);
// (2) two-phase split-K reduce for 4x parallelism in the latency-bound phase.
#define B_DIM   256
#define N_DIM   1024
#define K_DIM   16384
#define TILE_M  128
#define TILE_N  128
#define TILE_K  32
#define SPLITK  8
#define K_PER_CTA (K_DIM / SPLITK)       // 2048
#define NITER   (K_PER_CTA / TILE_K)     // 64
#define NTHREADS 512

// Smem tile: 128 rows x 32 halfs (64 B), padded stride 80 B (16-aligned;
// 80*r mod 128 covers 8 distinct 16B banks -> conflict-free ldmatrix).
#define ROW_HB   80
#define TILE_HB  (128 * ROW_HB)           // 10240 B
#define STAGE_HB (2 * TILE_HB)            // A + B per stage
#define SMEM_BYTES (2 * STAGE_HB)         // double buffer = 40960 B

#define HALF_ELEMS (B_DIM * N_DIM / 2)    // float2 count = 131072

__device__ float g_part[SPLITK * B_DIM * N_DIM];
__device__ float g_part2[2 * B_DIM * N_DIM];   // phase-1 halves (float2-addressed)

__device__ __forceinline__ uint32_t smem_u32(const void* p) {
    uint32_t a;
    asm("{ .reg .u64 t; cvta.to.shared.u64 t, %1; cvt.u32.u64 %0, t; }" : "=r"(a) : "l"(p));
    return a;
}

__device__ __forceinline__ void ldmx4(uint32_t* r, uint32_t addr) {
    asm volatile("ldmatrix.sync.aligned.m8n8.x4.shared.b16 {%0,%1,%2,%3}, [%4];"
                 : "=r"(r[0]), "=r"(r[1]), "=r"(r[2]), "=r"(r[3]) : "r"(addr));
}

__device__ __forceinline__ void mma16816(float* d, const uint32_t* a, const uint32_t* b) {
    asm volatile(
        "mma.sync.aligned.m16n8k16.row.col.f32.f16.f16.f32 "
        "{%0,%1,%2,%3}, {%4,%5,%6,%7}, {%8,%9}, {%0,%1,%2,%3};"
        : "+f"(d[0]), "+f"(d[1]), "+f"(d[2]), "+f"(d[3])
        : "r"(a[0]), "r"(a[1]), "r"(a[2]), "r"(a[3]), "r"(b[0]), "r"(b[1]));
}

__device__ __forceinline__ uint2 pack4h(float4 v) {
    __half2 lo = __floats2half2_rn(v.x, v.y);
    __half2 hi = __floats2half2_rn(v.z, v.w);
    uint2 r;
    r.x = *(uint32_t*)&lo;
    r.y = *(uint32_t*)&hi;
    return r;
}

__global__ void __launch_bounds__(NTHREADS, 1)
StreamingConv_gemm_kernel(const float* __restrict__ A, const float* __restrict__ W)
{
    __shared__ __align__(16) char smem[SMEM_BYTES];
    const uint32_t sb = smem_u32(smem);

    const int tid = threadIdx.x;
    const int lane = tid & 31;
    const int wid = tid >> 5;
    const int wm = wid >> 2;          // 0..3 -> 32-row band of M
    const int wn = wid & 3;           // 0..3 -> 32-col band of N

    const int m0 = blockIdx.y * TILE_M;
    const int n0 = blockIdx.x * TILE_N;
    const int sk = blockIdx.z;
    const size_t kbase = (size_t)sk * K_PER_CTA;

    // ---- gmem load mapping: 2 float4 for A + 2 for W per thread per iter ----
    const float* pa[2];
    const float* pb[2];
    uint32_t sts_off[2];
    #pragma unroll
    for (int i = 0; i < 2; i++) {
        const int idx = tid + NTHREADS * i;
        const int row = idx >> 3;     // 0..127
        const int c4  = idx & 7;      // float4 within 32-float row
        pa[i] = A + (size_t)(m0 + row) * K_DIM + kbase + c4 * 4;
        pb[i] = W + (size_t)(n0 + row) * K_DIM + kbase + c4 * 4;
        sts_off[i] = (uint32_t)(row * ROW_HB + c4 * 8);   // 4 halfs = 8 B
    }

    // ---- ldmatrix per-lane tile offsets (add ks*32 at use) ----
    uint32_t a_off[2];
    #pragma unroll
    for (int mt = 0; mt < 2; mt++)
        a_off[mt] = (uint32_t)((wm * 32 + mt * 16 + (lane & 15)) * ROW_HB + (lane >> 4) * 16);
    uint32_t b_off[2];
    #pragma unroll
    for (int p = 0; p < 2; p++)
        b_off[p] = (uint32_t)((wn * 32 + (2 * p + (lane >> 4)) * 8 + (lane & 7)) * ROW_HB
                              + ((lane >> 3) & 1) * 16);

    float acc[2][4][4];
    #pragma unroll
    for (int mt = 0; mt < 2; mt++)
        #pragma unroll
        for (int nt = 0; nt < 4; nt++)
            #pragma unroll
            for (int j = 0; j < 4; j++) acc[mt][nt][j] = 0.f;

    // ---- 2-deep register staging queue (raw fp32; cvt at STS) ----
    float4 qa[2][2], qb[2][2];
    #pragma unroll
    for (int d = 0; d < 2; d++) {
        const size_t ko = (size_t)d * TILE_K;
        #pragma unroll
        for (int i = 0; i < 2; i++) {
            qa[d][i] = *(const float4*)(pa[i] + ko);
            qb[d][i] = *(const float4*)(pb[i] + ko);
        }
    }
    #pragma unroll
    for (int i = 0; i < 2; i++) {
        *(uint2*)(smem + sts_off[i])           = pack4h(qa[0][i]);
        *(uint2*)(smem + TILE_HB + sts_off[i]) = pack4h(qb[0][i]);
    }
    __syncthreads();

    #pragma unroll 2
    for (int it = 0; it < NITER; ++it) {
        // LDG chunk it+2 into the slot holding chunk it (already stored last iter)
        if (it + 2 < NITER) {
            const size_t ko = (size_t)(it + 2) * TILE_K;
            const int d = it & 1;
            #pragma unroll
            for (int i = 0; i < 2; i++) {
                qa[d][i] = *(const float4*)(pa[i] + ko);
                qb[d][i] = *(const float4*)(pb[i] + ko);
            }
        }

        const uint32_t baseA = sb + (uint32_t)(it & 1) * STAGE_HB;
        const uint32_t baseB = baseA + TILE_HB;

        // ---- k16 step 0 ----
        {
            uint32_t afr[2][4], bfr[2][4];
            #pragma unroll
            for (int mt = 0; mt < 2; mt++) ldmx4(afr[mt], baseA + a_off[mt]);
            #pragma unroll
            for (int p = 0; p < 2; p++)  ldmx4(bfr[p], baseB + b_off[p]);
            #pragma unroll
            for (int mt = 0; mt < 2; mt++)
                #pragma unroll
                for (int nt = 0; nt < 4; nt++) {
                    uint32_t bb[2] = { bfr[nt >> 1][(nt & 1) * 2], bfr[nt >> 1][(nt & 1) * 2 + 1] };
                    mma16816(acc[mt][nt], afr[mt], bb);
                }
        }

        // ---- STS chunk it+1 between the MMA halves (ks1 MMAs cover drain) ----
        if (it + 1 < NITER) {
            const uint32_t nxt = (uint32_t)((it + 1) & 1) * STAGE_HB;
            const int d = (it + 1) & 1;
            #pragma unroll
            for (int i = 0; i < 2; i++) {
                *(uint2*)(smem + nxt + sts_off[i])           = pack4h(qa[d][i]);
                *(uint2*)(smem + nxt + TILE_HB + sts_off[i]) = pack4h(qb[d][i]);
            }
        }

        // ---- k16 step 1 ----
        {
            uint32_t afr[2][4], bfr[2][4];
            #pragma unroll
            for (int mt = 0; mt < 2; mt++) ldmx4(afr[mt], baseA + a_off[mt] + 32);
            #pragma unroll
            for (int p = 0; p < 2; p++)  ldmx4(bfr[p], baseB + b_off[p] + 32);
            #pragma unroll
            for (int mt = 0; mt < 2; mt++)
                #pragma unroll
                for (int nt = 0; nt < 4; nt++) {
                    uint32_t bb[2] = { bfr[nt >> 1][(nt & 1) * 2], bfr[nt >> 1][(nt & 1) * 2 + 1] };
                    mma16816(acc[mt][nt], afr[mt], bb);
                }
        }

        __syncthreads();
    }

    // ---- write split-K partials ----
    float* pbase = &g_part[(size_t)sk * (B_DIM * N_DIM)];
    #pragma unroll
    for (int mt = 0; mt < 2; mt++) {
        const int row0 = m0 + wm * 32 + mt * 16 + (lane >> 2);
        #pragma unroll
        for (int nt = 0; nt < 4; nt++) {
            const int col = n0 + wn * 32 + nt * 8 + 2 * (lane & 3);
            *(float2*)&pbase[(size_t)row0 * N_DIM + col]       = make_float2(acc[mt][nt][0], acc[mt][nt][1]);
            *(float2*)&pbase[(size_t)(row0 + 8) * N_DIM + col] = make_float2(acc[mt][nt][2], acc[mt][nt][3]);
        }
    }
}

// Phase 1: 262144 threads; thread (half, j) sums 4 splits of float2 j.
__global__ void StreamingConv_reduce_p1(int dummy)
{
    const int idx = blockIdx.x * blockDim.x + threadIdx.x;   // 0..262143
    const int half = idx >> 17;                              // 0 or 1
    const int j = idx & (HALF_ELEMS - 1);                    // float2 index
    const float2* p = (const float2*)g_part + (size_t)(half * 4) * HALF_ELEMS;
    float2 a0 = p[j];
    float2 a1 = p[(size_t)1 * HALF_ELEMS + j];
    float2 a2 = p[(size_t)2 * HALF_ELEMS + j];
    float2 a3 = p[(size_t)3 * HALF_ELEMS + j];
    float2 r = make_float2(a0.x + a1.x + a2.x + a3.x, a0.y + a1.y + a2.y + a3.y);
    ((float2*)g_part2)[(size_t)half * HALF_ELEMS + j] = r;
}

// Phase 2: 131072 threads; add the two halves.
__global__ void StreamingConv_reduce_p2(float* __restrict__ out)
{
    const int j = blockIdx.x * blockDim.x + threadIdx.x;     // float2 index
    const float2* q = (const float2*)g_part2;
    float2 a = q[j];
    float2 b = q[(size_t)HALF_ELEMS + j];
    ((float2*)out)[j] = make_float2(a.x + b.x, a.y + b.y);
}

extern "C" void kernel_launch(void* const* d_in, const int* in_sizes, int n_in,
                              void* d_out, int out_size)
{
    const float* A = (const float*)d_in[0];   // curr_input [256, 1024, 16]
    const float* W = (const float*)d_in[1];   // weight     [1024, 1024, 16]

    dim3 grid(N_DIM / TILE_N, B_DIM / TILE_M, SPLITK);   // (8, 2, 8) = 128 CTAs
    StreamingConv_gemm_kernel<<<grid, NTHREADS>>>(A, W);
    StreamingConv_reduce_p1<<<(2 * HALF_ELEMS) / 256, 256>>>(0);
    StreamingConv_reduce_p2<<<HALF_ELEMS / 256, 256>>>((float*)d_out);
}

// round 12
// speedup vs baseline: 1.1476x; 1.1117x over previous
#include <cuda_runtime.h>
#include <cuda_fp16.h>
#include <cstdint>

// D[b,o] = sum_ck A[b,ck] * W[o,ck] — GEMM M=256, N=1024, K=16384, fp32 I/O.
// fp16 operands (converted at STS), fp32 accumulate, mma.sync m16n8k16.
// BYTE-EXACT R4 mainloop (measured best GEMM 47.6us; every reorder attempt
// R5-R11 regressed ~10us): 512 threads / 16 warps, 128x128 CTA tile, 32x32
// warp tiles, TILE_K=32, double-buffered smem, 2-deep fp32 register staging,
// order LDG -> MMA(ks0,ks1) -> STS -> BAR.
// Plus the measured two-phase split-K reduce (3.3us vs 5.7us single-phase).
#define B_DIM   256
#define N_DIM   1024
#define K_DIM   16384
#define TILE_M  128
#define TILE_N  128
#define TILE_K  32
#define SPLITK  8
#define K_PER_CTA (K_DIM / SPLITK)       // 2048
#define NITER   (K_PER_CTA / TILE_K)     // 64
#define NTHREADS 512

// Smem tile: 128 rows x 32 halfs (64 B), padded stride 80 B (16-aligned;
// 80*r mod 128 covers 8 distinct 16B banks -> conflict-free ldmatrix).
#define ROW_HB   80
#define TILE_HB  (128 * ROW_HB)           // 10240 B
#define STAGE_HB (2 * TILE_HB)            // A + B per stage
#define SMEM_BYTES (2 * STAGE_HB)         // double buffer = 40960 B

#define HALF_ELEMS (B_DIM * N_DIM / 2)    // float2 count = 131072

__device__ float g_part[SPLITK * B_DIM * N_DIM];
__device__ float g_part2[2 * B_DIM * N_DIM];   // phase-1 halves (float2-addressed)

__device__ __forceinline__ uint32_t smem_u32(const void* p) {
    uint32_t a;
    asm("{ .reg .u64 t; cvta.to.shared.u64 t, %1; cvt.u32.u64 %0, t; }" : "=r"(a) : "l"(p));
    return a;
}

__device__ __forceinline__ void ldmx4(uint32_t* r, uint32_t addr) {
    asm volatile("ldmatrix.sync.aligned.m8n8.x4.shared.b16 {%0,%1,%2,%3}, [%4];"
                 : "=r"(r[0]), "=r"(r[1]), "=r"(r[2]), "=r"(r[3]) : "r"(addr));
}

__device__ __forceinline__ void mma16816(float* d, const uint32_t* a, const uint32_t* b) {
    asm volatile(
        "mma.sync.aligned.m16n8k16.row.col.f32.f16.f16.f32 "
        "{%0,%1,%2,%3}, {%4,%5,%6,%7}, {%8,%9}, {%0,%1,%2,%3};"
        : "+f"(d[0]), "+f"(d[1]), "+f"(d[2]), "+f"(d[3])
        : "r"(a[0]), "r"(a[1]), "r"(a[2]), "r"(a[3]), "r"(b[0]), "r"(b[1]));
}

__device__ __forceinline__ uint2 pack4h(float4 v) {
    __half2 lo = __floats2half2_rn(v.x, v.y);
    __half2 hi = __floats2half2_rn(v.z, v.w);
    uint2 r;
    r.x = *(uint32_t*)&lo;
    r.y = *(uint32_t*)&hi;
    return r;
}

__global__ void __launch_bounds__(NTHREADS, 1)
StreamingConv_gemm_kernel(const float* __restrict__ A, const float* __restrict__ W)
{
    __shared__ __align__(16) char smem[SMEM_BYTES];
    const uint32_t sb = smem_u32(smem);

    const int tid = threadIdx.x;
    const int lane = tid & 31;
    const int wid = tid >> 5;
    const int wm = wid >> 2;          // 0..3 -> 32-row band of M
    const int wn = wid & 3;           // 0..3 -> 32-col band of N

    const int m0 = blockIdx.y * TILE_M;
    const int n0 = blockIdx.x * TILE_N;
    const int sk = blockIdx.z;
    const size_t kbase = (size_t)sk * K_PER_CTA;

    // ---- gmem load mapping: 2 float4 for A + 2 for W per thread per iter ----
    const float* pa[2];
    const float* pb[2];
    uint32_t sts_off[2];
    #pragma unroll
    for (int i = 0; i < 2; i++) {
        const int idx = tid + NTHREADS * i;
        const int row = idx >> 3;     // 0..127
        const int c4  = idx & 7;      // float4 within 32-float row
        pa[i] = A + (size_t)(m0 + row) * K_DIM + kbase + c4 * 4;
        pb[i] = W + (size_t)(n0 + row) * K_DIM + kbase + c4 * 4;
        sts_off[i] = (uint32_t)(row * ROW_HB + c4 * 8);   // 4 halfs = 8 B
    }

    // ---- ldmatrix per-lane tile offsets (add ks*32 at use) ----
    uint32_t a_off[2];
    #pragma unroll
    for (int mt = 0; mt < 2; mt++)
        a_off[mt] = (uint32_t)((wm * 32 + mt * 16 + (lane & 15)) * ROW_HB + (lane >> 4) * 16);
    uint32_t b_off[2];
    #pragma unroll
    for (int p = 0; p < 2; p++)
        b_off[p] = (uint32_t)((wn * 32 + (2 * p + (lane >> 4)) * 8 + (lane & 7)) * ROW_HB
                              + ((lane >> 3) & 1) * 16);

    float acc[2][4][4];
    #pragma unroll
    for (int mt = 0; mt < 2; mt++)
        #pragma unroll
        for (int nt = 0; nt < 4; nt++)
            #pragma unroll
            for (int j = 0; j < 4; j++) acc[mt][nt][j] = 0.f;

    // ---- 2-deep register staging queue (raw fp32; cvt at STS) ----
    float4 qa[2][2], qb[2][2];
    #pragma unroll
    for (int d = 0; d < 2; d++) {
        const size_t ko = (size_t)d * TILE_K;
        #pragma unroll
        for (int i = 0; i < 2; i++) {
            qa[d][i] = *(const float4*)(pa[i] + ko);
            qb[d][i] = *(const float4*)(pb[i] + ko);
        }
    }
    #pragma unroll
    for (int i = 0; i < 2; i++) {
        *(uint2*)(smem + sts_off[i])           = pack4h(qa[0][i]);
        *(uint2*)(smem + TILE_HB + sts_off[i]) = pack4h(qb[0][i]);
    }
    __syncthreads();

    #pragma unroll 2
    for (int it = 0; it < NITER; ++it) {
        // LDG chunk it+2 into the slot holding chunk it (already stored last iter)
        if (it + 2 < NITER) {
            const size_t ko = (size_t)(it + 2) * TILE_K;
            const int d = it & 1;
            #pragma unroll
            for (int i = 0; i < 2; i++) {
                qa[d][i] = *(const float4*)(pa[i] + ko);
                qb[d][i] = *(const float4*)(pb[i] + ko);
            }
        }

        // compute current tile from stage it&1 (two k16 steps)
        const uint32_t baseA = sb + (uint32_t)(it & 1) * STAGE_HB;
        const uint32_t baseB = baseA + TILE_HB;
        #pragma unroll
        for (int ks = 0; ks < 2; ks++) {
            uint32_t afr[2][4], bfr[2][4];
            #pragma unroll
            for (int mt = 0; mt < 2; mt++) ldmx4(afr[mt], baseA + a_off[mt] + ks * 32);
            #pragma unroll
            for (int p = 0; p < 2; p++)  ldmx4(bfr[p], baseB + b_off[p] + ks * 32);
            #pragma unroll
            for (int mt = 0; mt < 2; mt++)
                #pragma unroll
                for (int nt = 0; nt < 4; nt++) {
                    uint32_t bb[2] = { bfr[nt >> 1][(nt & 1) * 2], bfr[nt >> 1][(nt & 1) * 2 + 1] };
                    mma16816(acc[mt][nt], afr[mt], bb);
                }
        }

        // convert + store chunk it+1 (loaded 1 full iter ago) into other stage
        if (it + 1 < NITER) {
            const uint32_t nxt = (uint32_t)((it + 1) & 1) * STAGE_HB;
            const int d = (it + 1) & 1;
            #pragma unroll
            for (int i = 0; i < 2; i++) {
                *(uint2*)(smem + nxt + sts_off[i])           = pack4h(qa[d][i]);
                *(uint2*)(smem + nxt + TILE_HB + sts_off[i]) = pack4h(qb[d][i]);
            }
        }
        __syncthreads();
    }

    // ---- write split-K partials ----
    float* pbase = &g_part[(size_t)sk * (B_DIM * N_DIM)];
    #pragma unroll
    for (int mt = 0; mt < 2; mt++) {
        const int row0 = m0 + wm * 32 + mt * 16 + (lane >> 2);
        #pragma unroll
        for (int nt = 0; nt < 4; nt++) {
            const int col = n0 + wn * 32 + nt * 8 + 2 * (lane & 3);
            *(float2*)&pbase[(size_t)row0 * N_DIM + col]       = make_float2(acc[mt][nt][0], acc[mt][nt][1]);
            *(float2*)&pbase[(size_t)(row0 + 8) * N_DIM + col] = make_float2(acc[mt][nt][2], acc[mt][nt][3]);
        }
    }
}

// Phase 1: 262144 threads; thread (half, j) sums 4 splits of float2 j.
__global__ void StreamingConv_reduce_p1(int dummy)
{
    const int idx = blockIdx.x * blockDim.x + threadIdx.x;   // 0..262143
    const int half = idx >> 17;                              // 0 or 1
    const int j = idx & (HALF_ELEMS - 1);                    // float2 index
    const float2* p = (const float2*)g_part + (size_t)(half * 4) * HALF_ELEMS;
    float2 a0 = p[j];
    float2 a1 = p[(size_t)1 * HALF_ELEMS + j];
    float2 a2 = p[(size_t)2 * HALF_ELEMS + j];
    float2 a3 = p[(size_t)3 * HALF_ELEMS + j];
    float2 r = make_float2(a0.x + a1.x + a2.x + a3.x, a0.y + a1.y + a2.y + a3.y);
    ((float2*)g_part2)[(size_t)half * HALF_ELEMS + j] = r;
}

// Phase 2: 131072 threads; add the two halves.
__global__ void StreamingConv_reduce_p2(float* __restrict__ out)
{
    const int j = blockIdx.x * blockDim.x + threadIdx.x;     // float2 index
    const float2* q = (const float2*)g_part2;
    float2 a = q[j];
    float2 b = q[(size_t)HALF_ELEMS + j];
    ((float2*)out)[j] = make_float2(a.x + b.x, a.y + b.y);
}

extern "C" void kernel_launch(void* const* d_in, const int* in_sizes, int n_in,
                              void* d_out, int out_size)
{
    const float* A = (const float*)d_in[0];   // curr_input [256, 1024, 16]
    const float* W = (const float*)d_in[1];   // weight     [1024, 1024, 16]

    dim3 grid(N_DIM / TILE_N, B_DIM / TILE_M, SPLITK);   // (8, 2, 8) = 128 CTAs
    StreamingConv_gemm_kernel<<<grid, NTHREADS>>>(A, W);
    StreamingConv_reduce_p1<<<(2 * HALF_ELEMS) / 256, 256>>>(0);
    StreamingConv_reduce_p2<<<HALF_ELEMS / 256, 256>>>((float*)d_out);
}

// round 13
// speedup vs baseline: 1.1846x; 1.0323x over previous
#include <cuda_runtime.h>
#include <cuda_fp16.h>
#include <cstdint>

// D[b,o] = sum_ck A[b,ck] * W[o,ck] — GEMM M=256, N=1024, K=16384, fp32 I/O.
// fp16 operands (converted at STS), fp32 accumulate, mma.sync m16n8k16.
// BYTE-EXACT R4 mainloop (measured 47.6/50.9us; every reorder regressed):
// 512 threads / 16 warps, 128x128 CTA tile, 32x32 warp tiles, TILE_K=32,
// double-buffered smem, 2-deep fp32 register staging, LDG->MMA->STS->BAR.
// R13 change: split-K combination via atomicAdd epilogue directly into out
// (after a zero-init kernel) — removes the 4.4us reduce launches entirely;
// the ~1us of REDG tail overlaps with other CTAs' mainloops.
#define B_DIM   256
#define N_DIM   1024
#define K_DIM   16384
#define TILE_M  128
#define TILE_N  128
#define TILE_K  32
#define SPLITK  8
#define K_PER_CTA (K_DIM / SPLITK)       // 2048
#define NITER   (K_PER_CTA / TILE_K)     // 64
#define NTHREADS 512

// Smem tile: 128 rows x 32 halfs (64 B), padded stride 80 B (16-aligned;
// 80*r mod 128 covers 8 distinct 16B banks -> conflict-free ldmatrix).
#define ROW_HB   80
#define TILE_HB  (128 * ROW_HB)           // 10240 B
#define STAGE_HB (2 * TILE_HB)            // A + B per stage
#define SMEM_BYTES (2 * STAGE_HB)         // double buffer = 40960 B

__device__ __forceinline__ uint32_t smem_u32(const void* p) {
    uint32_t a;
    asm("{ .reg .u64 t; cvta.to.shared.u64 t, %1; cvt.u32.u64 %0, t; }" : "=r"(a) : "l"(p));
    return a;
}

__device__ __forceinline__ void ldmx4(uint32_t* r, uint32_t addr) {
    asm volatile("ldmatrix.sync.aligned.m8n8.x4.shared.b16 {%0,%1,%2,%3}, [%4];"
                 : "=r"(r[0]), "=r"(r[1]), "=r"(r[2]), "=r"(r[3]) : "r"(addr));
}

__device__ __forceinline__ void mma16816(float* d, const uint32_t* a, const uint32_t* b) {
    asm volatile(
        "mma.sync.aligned.m16n8k16.row.col.f32.f16.f16.f32 "
        "{%0,%1,%2,%3}, {%4,%5,%6,%7}, {%8,%9}, {%0,%1,%2,%3};"
        : "+f"(d[0]), "+f"(d[1]), "+f"(d[2]), "+f"(d[3])
        : "r"(a[0]), "r"(a[1]), "r"(a[2]), "r"(a[3]), "r"(b[0]), "r"(b[1]));
}

__device__ __forceinline__ uint2 pack4h(float4 v) {
    __half2 lo = __floats2half2_rn(v.x, v.y);
    __half2 hi = __floats2half2_rn(v.z, v.w);
    uint2 r;
    r.x = *(uint32_t*)&lo;
    r.y = *(uint32_t*)&hi;
    return r;
}

__global__ void StreamingConv_zero_kernel(float* __restrict__ out)
{
    const int idx = blockIdx.x * blockDim.x + threadIdx.x;   // float4 index
    ((float4*)out)[idx] = make_float4(0.f, 0.f, 0.f, 0.f);
}

__global__ void __launch_bounds__(NTHREADS, 1)
StreamingConv_gemm_kernel(const float* __restrict__ A, const float* __restrict__ W,
                          float* __restrict__ out)
{
    __shared__ __align__(16) char smem[SMEM_BYTES];
    const uint32_t sb = smem_u32(smem);

    const int tid = threadIdx.x;
    const int lane = tid & 31;
    const int wid = tid >> 5;
    const int wm = wid >> 2;          // 0..3 -> 32-row band of M
    const int wn = wid & 3;           // 0..3 -> 32-col band of N

    const int m0 = blockIdx.y * TILE_M;
    const int n0 = blockIdx.x * TILE_N;
    const int sk = blockIdx.z;
    const size_t kbase = (size_t)sk * K_PER_CTA;

    // ---- gmem load mapping: 2 float4 for A + 2 for W per thread per iter ----
    const float* pa[2];
    const float* pb[2];
    uint32_t sts_off[2];
    #pragma unroll
    for (int i = 0; i < 2; i++) {
        const int idx = tid + NTHREADS * i;
        const int row = idx >> 3;     // 0..127
        const int c4  = idx & 7;      // float4 within 32-float row
        pa[i] = A + (size_t)(m0 + row) * K_DIM + kbase + c4 * 4;
        pb[i] = W + (size_t)(n0 + row) * K_DIM + kbase + c4 * 4;
        sts_off[i] = (uint32_t)(row * ROW_HB + c4 * 8);   // 4 halfs = 8 B
    }

    // ---- ldmatrix per-lane tile offsets (add ks*32 at use) ----
    uint32_t a_off[2];
    #pragma unroll
    for (int mt = 0; mt < 2; mt++)
        a_off[mt] = (uint32_t)((wm * 32 + mt * 16 + (lane & 15)) * ROW_HB + (lane >> 4) * 16);
    uint32_t b_off[2];
    #pragma unroll
    for (int p = 0; p < 2; p++)
        b_off[p] = (uint32_t)((wn * 32 + (2 * p + (lane >> 4)) * 8 + (lane & 7)) * ROW_HB
                              + ((lane >> 3) & 1) * 16);

    float acc[2][4][4];
    #pragma unroll
    for (int mt = 0; mt < 2; mt++)
        #pragma unroll
        for (int nt = 0; nt < 4; nt++)
            #pragma unroll
            for (int j = 0; j < 4; j++) acc[mt][nt][j] = 0.f;

    // ---- 2-deep register staging queue (raw fp32; cvt at STS) ----
    float4 qa[2][2], qb[2][2];
    #pragma unroll
    for (int d = 0; d < 2; d++) {
        const size_t ko = (size_t)d * TILE_K;
        #pragma unroll
        for (int i = 0; i < 2; i++) {
            qa[d][i] = *(const float4*)(pa[i] + ko);
            qb[d][i] = *(const float4*)(pb[i] + ko);
        }
    }
    #pragma unroll
    for (int i = 0; i < 2; i++) {
        *(uint2*)(smem + sts_off[i])           = pack4h(qa[0][i]);
        *(uint2*)(smem + TILE_HB + sts_off[i]) = pack4h(qb[0][i]);
    }
    __syncthreads();

    #pragma unroll 2
    for (int it = 0; it < NITER; ++it) {
        // LDG chunk it+2 into the slot holding chunk it (already stored last iter)
        if (it + 2 < NITER) {
            const size_t ko = (size_t)(it + 2) * TILE_K;
            const int d = it & 1;
            #pragma unroll
            for (int i = 0; i < 2; i++) {
                qa[d][i] = *(const float4*)(pa[i] + ko);
                qb[d][i] = *(const float4*)(pb[i] + ko);
            }
        }

        // compute current tile from stage it&1 (two k16 steps)
        const uint32_t baseA = sb + (uint32_t)(it & 1) * STAGE_HB;
        const uint32_t baseB = baseA + TILE_HB;
        #pragma unroll
        for (int ks = 0; ks < 2; ks++) {
            uint32_t afr[2][4], bfr[2][4];
            #pragma unroll
            for (int mt = 0; mt < 2; mt++) ldmx4(afr[mt], baseA + a_off[mt] + ks * 32);
            #pragma unroll
            for (int p = 0; p < 2; p++)  ldmx4(bfr[p], baseB + b_off[p] + ks * 32);
            #pragma unroll
            for (int mt = 0; mt < 2; mt++)
                #pragma unroll
                for (int nt = 0; nt < 4; nt++) {
                    uint32_t bb[2] = { bfr[nt >> 1][(nt & 1) * 2], bfr[nt >> 1][(nt & 1) * 2 + 1] };
                    mma16816(acc[mt][nt], afr[mt], bb);
                }
        }

        // convert + store chunk it+1 (loaded 1 full iter ago) into other stage
        if (it + 1 < NITER) {
            const uint32_t nxt = (uint32_t)((it + 1) & 1) * STAGE_HB;
            const int d = (it + 1) & 1;
            #pragma unroll
            for (int i = 0; i < 2; i++) {
                *(uint2*)(smem + nxt + sts_off[i])           = pack4h(qa[d][i]);
                *(uint2*)(smem + nxt + TILE_HB + sts_off[i]) = pack4h(qb[d][i]);
            }
        }
        __syncthreads();
    }

    // ---- epilogue: atomically accumulate this split's tile into out ----
    #pragma unroll
    for (int mt = 0; mt < 2; mt++) {
        const int row0 = m0 + wm * 32 + mt * 16 + (lane >> 2);
        #pragma unroll
        for (int nt = 0; nt < 4; nt++) {
            const int col = n0 + wn * 32 + nt * 8 + 2 * (lane & 3);
            atomicAdd(&out[(size_t)row0 * N_DIM + col],           acc[mt][nt][0]);
            atomicAdd(&out[(size_t)row0 * N_DIM + col + 1],       acc[mt][nt][1]);
            atomicAdd(&out[(size_t)(row0 + 8) * N_DIM + col],     acc[mt][nt][2]);
            atomicAdd(&out[(size_t)(row0 + 8) * N_DIM + col + 1], acc[mt][nt][3]);
        }
    }
}

extern "C" void kernel_launch(void* const* d_in, const int* in_sizes, int n_in,
                              void* d_out, int out_size)
{
    const float* A = (const float*)d_in[0];   // curr_input [256, 1024, 16]
    const float* W = (const float*)d_in[1];   // weight     [1024, 1024, 16]
    float* out = (float*)d_out;               // [256, 1024]

    StreamingConv_zero_kernel<<<(B_DIM * N_DIM / 4) / 256, 256>>>(out);

    dim3 grid(N_DIM / TILE_N, B_DIM / TILE_M, SPLITK);   // (8, 2, 8) = 128 CTAs
    StreamingConv_gemm_kernel<<<grid, NTHREADS>>>(A, W, out);
}

// round 14
// speedup vs baseline: 1.2371x; 1.0443x over previous
#include <cuda_runtime.h>
#include <cuda_fp16.h>
#include <cstdint>

// D[b,o] = sum_ck A[b,ck] * W[o,ck] — GEMM M=256, N=1024, K=16384, fp32 I/O.
// fp16 operands (converted at STS), fp32 accumulate, mma.sync m16n8k16.
// R14: CTA tile 128x256 with 16 warps of 32x64 warp tiles — cuts LDSM bytes
// per MAC by 25% (L1 pipe is the measured 66% bottleneck) and halves barriers
// (NITER=32). Order preserved from measured-best R4: LDG -> MMA -> STS -> BAR.
// 1-deep register queue (iter body ~2x longer; LDG latency still covered).
// SPLITK=16 -> (4,2,16) = 128 CTAs = one wave. Atomic epilogue (R13-proven).
#define B_DIM   256
#define N_DIM   1024
#define K_DIM   16384
#define TILE_M  128
#define TILE_N  256
#define TILE_K  32
#define SPLITK  16
#define K_PER_CTA (K_DIM / SPLITK)       // 1024
#define NITER   (K_PER_CTA / TILE_K)     // 32
#define NTHREADS 512

// Smem rows: 32 halfs (64 B) padded to stride 80 B -> conflict-free ldmatrix.
#define ROW_HB   80
#define A_HB     (128 * ROW_HB)           // 10240 B (A: 128 rows)
#define B_HB     (256 * ROW_HB)           // 20480 B (B: 256 rows)
#define STAGE_HB (A_HB + B_HB)            // 30720 B
#define SMEM_BYTES (2 * STAGE_HB)         // 61440 B (dynamic)

__device__ __forceinline__ uint32_t smem_u32(const void* p) {
    uint32_t a;
    asm("{ .reg .u64 t; cvta.to.shared.u64 t, %1; cvt.u32.u64 %0, t; }" : "=r"(a) : "l"(p));
    return a;
}

__device__ __forceinline__ void ldmx4(uint32_t* r, uint32_t addr) {
    asm volatile("ldmatrix.sync.aligned.m8n8.x4.shared.b16 {%0,%1,%2,%3}, [%4];"
                 : "=r"(r[0]), "=r"(r[1]), "=r"(r[2]), "=r"(r[3]) : "r"(addr));
}

__device__ __forceinline__ void mma16816(float* d, const uint32_t* a, const uint32_t* b) {
    asm volatile(
        "mma.sync.aligned.m16n8k16.row.col.f32.f16.f16.f32 "
        "{%0,%1,%2,%3}, {%4,%5,%6,%7}, {%8,%9}, {%0,%1,%2,%3};"
        : "+f"(d[0]), "+f"(d[1]), "+f"(d[2]), "+f"(d[3])
        : "r"(a[0]), "r"(a[1]), "r"(a[2]), "r"(a[3]), "r"(b[0]), "r"(b[1]));
}

__device__ __forceinline__ uint2 pack4h(float4 v) {
    __half2 lo = __floats2half2_rn(v.x, v.y);
    __half2 hi = __floats2half2_rn(v.z, v.w);
    uint2 r;
    r.x = *(uint32_t*)&lo;
    r.y = *(uint32_t*)&hi;
    return r;
}

__global__ void StreamingConv_zero_kernel(float* __restrict__ out)
{
    const int idx = blockIdx.x * blockDim.x + threadIdx.x;   // float4 index
    ((float4*)out)[idx] = make_float4(0.f, 0.f, 0.f, 0.f);
}

__global__ void __launch_bounds__(NTHREADS, 1)
StreamingConv_gemm_kernel(const float* __restrict__ A, const float* __restrict__ W,
                          float* __restrict__ out)
{
    extern __shared__ __align__(16) char smem[];
    const uint32_t sb = smem_u32(smem);

    const int tid = threadIdx.x;
    const int lane = tid & 31;
    const int wid = tid >> 5;
    const int wm = wid >> 2;          // 0..3 -> 32-row band of M
    const int wn = wid & 3;           // 0..3 -> 64-col band of N

    const int m0 = blockIdx.y * TILE_M;
    const int n0 = blockIdx.x * TILE_N;
    const int sk = blockIdx.z;
    const size_t kbase = (size_t)sk * K_PER_CTA;

    // ---- gmem load mapping ----
    // A tile: 128 rows x 8 float4 = 1024 float4 -> 2 per thread
    // B tile: 256 rows x 8 float4 = 2048 float4 -> 4 per thread
    const float* pa[2];
    uint32_t sa_off[2];
    #pragma unroll
    for (int i = 0; i < 2; i++) {
        const int idx = tid + NTHREADS * i;
        const int row = idx >> 3;     // 0..127
        const int c4  = idx & 7;
        pa[i] = A + (size_t)(m0 + row) * K_DIM + kbase + c4 * 4;
        sa_off[i] = (uint32_t)(row * ROW_HB + c4 * 8);
    }
    const float* pb[4];
    uint32_t sbo_off[4];
    #pragma unroll
    for (int i = 0; i < 4; i++) {
        const int idx = tid + NTHREADS * i;
        const int row = idx >> 3;     // 0..255
        const int c4  = idx & 7;
        pb[i] = W + (size_t)(n0 + row) * K_DIM + kbase + c4 * 4;
        sbo_off[i] = (uint32_t)(A_HB + row * ROW_HB + c4 * 8);
    }

    // ---- ldmatrix per-lane tile offsets (add ks*32 at use) ----
    uint32_t a_off[2];
    #pragma unroll
    for (int mt = 0; mt < 2; mt++)
        a_off[mt] = (uint32_t)((wm * 32 + mt * 16 + (lane & 15)) * ROW_HB + (lane >> 4) * 16);
    uint32_t b_off[4];
    #pragma unroll
    for (int pj = 0; pj < 4; pj++)
        b_off[pj] = (uint32_t)(A_HB + (wn * 64 + (2 * pj + (lane >> 4)) * 8 + (lane & 7)) * ROW_HB
                               + ((lane >> 3) & 1) * 16);

    float acc[2][8][4];
    #pragma unroll
    for (int mt = 0; mt < 2; mt++)
        #pragma unroll
        for (int nt = 0; nt < 8; nt++)
            #pragma unroll
            for (int j = 0; j < 4; j++) acc[mt][nt][j] = 0.f;

    // ---- prologue: chunk 0 -> stage 0 ----
    #pragma unroll
    for (int i = 0; i < 2; i++)
        *(uint2*)(smem + sa_off[i]) = pack4h(*(const float4*)pa[i]);
    #pragma unroll
    for (int i = 0; i < 4; i++)
        *(uint2*)(smem + sbo_off[i]) = pack4h(*(const float4*)pb[i]);
    __syncthreads();

    #pragma unroll 2
    for (int it = 0; it < NITER; ++it) {
        // 1-deep queue: LDG chunk it+1 (raw fp32; cvt at STS after the MMAs)
        float4 qa[2], qb[4];
        if (it + 1 < NITER) {
            const size_t ko = (size_t)(it + 1) * TILE_K;
            #pragma unroll
            for (int i = 0; i < 2; i++) qa[i] = *(const float4*)(pa[i] + ko);
            #pragma unroll
            for (int i = 0; i < 4; i++) qb[i] = *(const float4*)(pb[i] + ko);
        }

        // compute current tile from stage it&1 (two k16 steps)
        const uint32_t base = sb + (uint32_t)(it & 1) * STAGE_HB;
        #pragma unroll
        for (int ks = 0; ks < 2; ks++) {
            uint32_t afr[2][4], bfr[4][4];
            #pragma unroll
            for (int mt = 0; mt < 2; mt++) ldmx4(afr[mt], base + a_off[mt] + ks * 32);
            #pragma unroll
            for (int pj = 0; pj < 4; pj++) ldmx4(bfr[pj], base + b_off[pj] + ks * 32);
            #pragma unroll
            for (int mt = 0; mt < 2; mt++)
                #pragma unroll
                for (int nt = 0; nt < 8; nt++) {
                    uint32_t bb[2] = { bfr[nt >> 1][(nt & 1) * 2], bfr[nt >> 1][(nt & 1) * 2 + 1] };
                    mma16816(acc[mt][nt], afr[mt], bb);
                }
        }

        // convert + store chunk it+1 into the other stage
        if (it + 1 < NITER) {
            const uint32_t nxt = (uint32_t)((it + 1) & 1) * STAGE_HB;
            #pragma unroll
            for (int i = 0; i < 2; i++)
                *(uint2*)(smem + nxt + sa_off[i] - 0) = pack4h(qa[i]);
            #pragma unroll
            for (int i = 0; i < 4; i++)
                *(uint2*)(smem + nxt + sbo_off[i]) = pack4h(qb[i]);
        }
        __syncthreads();
    }

    // ---- epilogue: atomically accumulate this split's tile into out ----
    #pragma unroll
    for (int mt = 0; mt < 2; mt++) {
        const int row0 = m0 + wm * 32 + mt * 16 + (lane >> 2);
        #pragma unroll
        for (int nt = 0; nt < 8; nt++) {
            const int col = n0 + wn * 64 + nt * 8 + 2 * (lane & 3);
            atomicAdd(&out[(size_t)row0 * N_DIM + col],           acc[mt][nt][0]);
            atomicAdd(&out[(size_t)row0 * N_DIM + col + 1],       acc[mt][nt][1]);
            atomicAdd(&out[(size_t)(row0 + 8) * N_DIM + col],     acc[mt][nt][2]);
            atomicAdd(&out[(size_t)(row0 + 8) * N_DIM + col + 1], acc[mt][nt][3]);
        }
    }
}

extern "C" void kernel_launch(void* const* d_in, const int* in_sizes, int n_in,
                              void* d_out, int out_size)
{
    const float* A = (const float*)d_in[0];   // curr_input [256, 1024, 16]
    const float* W = (const float*)d_in[1];   // weight     [1024, 1024, 16]
    float* out = (float*)d_out;               // [256, 1024]

    static int attr_set = 0;
    if (!attr_set) {
        cudaFuncSetAttribute(StreamingConv_gemm_kernel,
                             cudaFuncAttributeMaxDynamicSharedMemorySize, SMEM_BYTES);
        attr_set = 1;
    }

    StreamingConv_zero_kernel<<<(B_DIM * N_DIM / 4) / 256, 256>>>(out);

    dim3 grid(N_DIM / TILE_N, B_DIM / TILE_M, SPLITK);   // (4, 2, 16) = 128 CTAs
    StreamingConv_gemm_kernel<<<grid, NTHREADS, SMEM_BYTES>>>(A, W, out);
}